// round 11
// baseline (speedup 1.0000x reference)
#include <cuda_runtime.h>
#include <cstdint>

// PEPS 6x6, D=3, B=16 — quadrant decomposition, cluster of 2 CTAs per config.
// Left CTA (rank0): threads 0-255 = TL quadrant, 256-511 = BL. Right CTA:
// TR, BR (mirrored -> identical code). Per quadrant: closed-form fused row 0,
// then 6 local steps (state = 243 float4 groups). Merge P[j,k] =
// sum_v top[v,j]*bot[v,k] intra-CTA, split over v across 486 threads
// (P1: v<14, P2: v>=14). One cross-CTA hop: right pushes Q1,Q2 into left's
// QR, signals one mbarrier; left computes sum (P1+P2)*(Q1+Q2), writes.
// Gather lines are L1-prefetched at kernel entry (line address is independent
// of the spin offset), and sOff is computed straight from gmem (no spin pass).

#define NTH 512
#define ATF 108

__device__ __forceinline__ float dot3(float4 a, float4 b) {
    return a.x * b.x + a.y * b.y + a.z * b.z;
}

__device__ __forceinline__ uint32_t smem_u32(const void* p) {
    uint32_t a;
    asm("{ .reg .u64 t; cvta.to.shared.u64 t, %1; cvt.u32.u64 %0, t; }"
        : "=r"(a) : "l"(p));
    return a;
}

__device__ __forceinline__ uint32_t mapa_rank(uint32_t laddr, uint32_t rank) {
    uint32_t r;
    asm volatile("mapa.shared::cluster.u32 %0, %1, %2;" : "=r"(r) : "r"(laddr), "r"(rank));
    return r;
}

__device__ __forceinline__ void st_cluster_raw(uint32_t raddr, float v) {
    asm volatile("st.shared::cluster.f32 [%0], %1;" :: "r"(raddr), "f"(v) : "memory");
}

__device__ __forceinline__ void mbar_init(uint32_t addr, uint32_t cnt) {
    asm volatile("mbarrier.init.shared.b64 [%0], %1;" :: "r"(addr), "r"(cnt) : "memory");
}

__device__ __forceinline__ void mbar_arrive_remote(uint32_t laddr, uint32_t rank) {
    asm volatile(
        "{ .reg .b32 ra;\n\t"
        "  mapa.shared::cluster.u32 ra, %0, %1;\n\t"
        "  mbarrier.arrive.shared::cluster.b64 _, [ra]; }"
        :: "r"(laddr), "r"(rank) : "memory");
}

__device__ __forceinline__ void mbar_wait0(uint32_t addr) {
    uint32_t done = 0;
    while (!done) {
        asm volatile(
            "{ .reg .pred p;\n\t"
            "  mbarrier.try_wait.parity.shared.b64 p, [%1], %2, 0x989680;\n\t"
            "  selp.b32 %0, 1, 0, p; }"
            : "=r"(done) : "r"(addr), "r"(0u) : "memory");
    }
}

#define FENCE_CLUSTER() asm volatile("fence.acq_rel.cluster;" ::: "memory")

__global__ __launch_bounds__(NTH, 1) __cluster_dims__(2, 1, 1)
void peps_quad2_kernel(const int* __restrict__ xcfg,
                       const float* __restrict__ T,
                       float* __restrict__ out) {
    __shared__ float4 S0[2][243];
    __shared__ float4 S1[2][243];
    __shared__ float  At[2][9 * ATF];
    __shared__ float  P[2][729];
    __shared__ float  QR[2][729];       // left CTA: remote writes only
    __shared__ int    sOff[36];
    __shared__ float  red[16];
    __shared__ uint64_t mb_q;

    const int t  = threadIdx.x;
    const int b  = blockIdx.x >> 1;
    const int qi = t >> 8;
    const int lt = t & 255;
    uint32_t rank;
    asm("mov.u32 %0, %%cluster_ctarank;" : "=r"(rank));
    const int right = (int)rank;

    const uint32_t a_mb = smem_u32(&mb_q);

    // sOff straight from gmem (t<36): 5 parallel L2 loads, no spin-smem pass.
    if (t < 36) {
        const int* xb = xcfg + b * 36;
        int xx = t / 6, yy = t % 6;
        int p  = xb[t];
        int pu = (xx > 0) ? xb[t - 6] : 0;
        int pd = (xx < 5) ? xb[t + 6] : 0;
        int pl = (yy > 0) ? xb[t - 1] : 0;
        int pr = (yy < 5) ? xb[t + 1] : 0;
        sOff[t] = (((p * 2 + pu) * 2 + pd) * 2 + pl) * 2 + pr;
    }
    if (t == NTH - 1) mbar_init(a_mb, 1);

    // L1 prefetch of all gather lines (addresses independent of sOff):
    // element (q2, s, e) lives in the 128B line at T + site*2592 + e*32.
    for (int i = t; i < 1458; i += NTH) {
        int q2 = i / 729, j = i - q2 * 729;
        int s = j / 81, e = j - s * 81;
        int x = q2    ? 5 - s / 3 : s / 3;
        int y = right ? 5 - s % 3 : s % 3;
        const float* p = T + (x * 6 + y) * 2592 + e * 32;
        asm volatile("prefetch.global.L1 [%0];" :: "l"(p));
    }
    __syncthreads();
    asm volatile("barrier.cluster.arrive.aligned;" ::: "memory");

    // Gather both quadrants' tensors: At[q][s][o][hp][a][ln].
    for (int i = t; i < 2 * 9 * ATF; i += NTH) {
        int q2 = i / 972, j = i - q2 * 972;
        int s = j / ATF, r = j - s * ATF;
        int o  = r / 36;  r -= o * 36;
        int hp = r / 12;  r -= hp * 12;
        int a  = r >> 2,  ln = r & 3;
        float v = 0.0f;
        if (ln < 3) {
            int x = q2    ? 5 - s / 3 : s / 3;
            int y = right ? 5 - s % 3 : s % 3;
            int u  = q2 ? o : a;
            int d  = q2 ? a : o;
            int l  = right ? hp : ln;
            int rr = right ? ln : hp;
            int site = x * 6 + y;
            v = T[site * 2592 + (((u * 3 + d) * 3 + l) * 3 + rr) * 32 + sOff[site]];
        }
        At[q2][j] = v;
    }
    __syncthreads();

    const float* Aq = At[qi];

    // Fused row 0 (sites 0,1,2): state(d0@81,d1@27,d2@9,r2@3) lanes=(v,0,0)
    if (lt < 243) {
        float v = 0.0f;
        if (lt % 3 == 0) {
            int d0 = lt / 81, d1 = (lt / 27) % 3, d2 = (lt / 9) % 3, r2 = (lt / 3) % 3;
            const float* A0 = Aq + d0 * 36;
            const float* A1 = Aq + ATF + d1 * 36;
            const float* A2 = Aq + 2 * ATF + d2 * 36 + r2 * 12;
            float w0 = A0[0] * A1[0]  + A0[12] * A1[1]  + A0[24] * A1[2];
            float w1 = A0[0] * A1[12] + A0[12] * A1[13] + A0[24] * A1[14];
            float w2 = A0[0] * A1[24] + A0[12] * A1[25] + A0[24] * A1[26];
            v = w0 * A2[0] + w1 * A2[1] + w2 * A2[2];
        }
        S0[qi][lt] = make_float4(v, 0.0f, 0.0f, 0.0f);
    }
    asm volatile("barrier.cluster.wait.aligned;" ::: "memory");
    __syncthreads();

    // hoisted per-thread step indices (lt-based)
    const int d81 = lt / 81,        b81 = lt - d81 * 81;
    const int d27 = (lt / 27) % 3,  b27 = lt - d27 * 27;
    const int d9  = (lt / 9) % 3,   b9  = lt - d9 * 9;
    const int r3  = lt % 3;
    const int bc4 = (lt / 27) * 27 + ((lt / 3) % 3) * 3;

    const float4* Atv = (const float4*)Aq;
    float4* Sq0 = S0[qi];
    float4* Sq1 = S1[qi];

#define STEPL(SITE, D_, BASE, S3, RD, WR) { \
    if (lt < 243) { \
        float4 c0 = (RD)[BASE]; \
        float4 c1 = (RD)[BASE + (S3)]; \
        float4 c2 = (RD)[BASE + 2 * (S3)]; \
        const float4* Av = Atv + (SITE) * 27 + (D_) * 9; \
        float r0 = dot3(c0, Av[0]) + dot3(c1, Av[1]) + dot3(c2, Av[2]); \
        float r1 = dot3(c0, Av[3]) + dot3(c1, Av[4]) + dot3(c2, Av[5]); \
        float r2 = dot3(c0, Av[6]) + dot3(c1, Av[7]) + dot3(c2, Av[8]); \
        (WR)[lt] = make_float4(r0, r1, r2, 0.0f); \
    } \
    __syncthreads(); \
}

#define STEPC4(SITE, RD, WR) { \
    if (lt < 243) { \
        const float4* Av = Atv + (SITE) * 27 + d9 * 9 + r3 * 3; \
        float s_ = dot3((RD)[bc4], Av[0]) + dot3((RD)[bc4 + 9], Av[1]) \
                 + dot3((RD)[bc4 + 18], Av[2]); \
        (WR)[lt] = make_float4(s_, 0.0f, 0.0f, 0.0f); \
    } \
    __syncthreads(); \
}

    // row 1
    STEPL (3, d81, b81, 81, Sq0, Sq1)
    STEPL (4, d27, b27, 27, Sq1, Sq0)
    STEPC4(5,               Sq0, Sq1)
    // row 2
    STEPL (6, d81, b81, 81, Sq1, Sq0)
    STEPL (7, d27, b27, 27, Sq0, Sq1)
    STEPL (8, d9,  b9,   9, Sq1, Sq0)   // final state in S0[qi]
#undef STEPL
#undef STEPC4

    // Split-v merge over 486 threads: half h covers v in [h?14:0, h?27:14).
    // P_h[j*27+kg*3+{0,1,2}] = sum_{v in half} top[v*9+jg].(jl) * bot[v*9+kg].{x,y,z}
    if (t < 486) {
        int id = (t < 243) ? t : t - 243;
        int h  = (t < 243) ? 0 : 1;
        int j  = id / 9;
        int kg = id - 9 * j;
        int jg = j / 3, jl = j - 3 * jg;
        const float*  Stop = (const float*)S0[0];
        const float4* Sbot = S0[1];
        int v0 = h ? 14 : 0, v1e = h ? 27 : 14;
        float a0 = 0.0f, a1 = 0.0f, a2 = 0.0f;
        #pragma unroll
        for (int v1 = 0; v1 < 14; ++v1) {
            int v = v0 + v1;
            if (v < v1e) {
                float  l = Stop[(v * 9 + jg) * 4 + jl];
                float4 R = Sbot[v * 9 + kg];
                a0 += l * R.x; a1 += l * R.y; a2 += l * R.z;
            }
        }
        int o = j * 27 + kg * 3;
        if (right) {
            uint32_t ra = mapa_rank(smem_u32(&QR[h][o]), 0);
            st_cluster_raw(ra,     a0);
            st_cluster_raw(ra + 4, a1);
            st_cluster_raw(ra + 8, a2);
        } else {
            P[h][o] = a0; P[h][o + 1] = a1; P[h][o + 2] = a2;
        }
    }
    __syncthreads();

    if (right) {
        if (t == 0) { FENCE_CLUSTER(); mbar_arrive_remote(a_mb, 0); }
        return;
    }

    // Left CTA: wait for Q halves, dot, write.
    mbar_wait0(a_mb);
    FENCE_CLUSTER();
    {
        float s = 0.0f;
        for (int v = t; v < 729; v += NTH)
            s += (P[0][v] + P[1][v]) * (QR[0][v] + QR[1][v]);
        #pragma unroll
        for (int o = 16; o; o >>= 1) s += __shfl_xor_sync(0xFFFFFFFFu, s, o);
        if ((t & 31) == 0) red[t >> 5] = s;
        __syncthreads();
        if (t == 0) {
            float tt = 0.0f;
            #pragma unroll
            for (int w = 0; w < 16; ++w) tt += red[w];
            out[b] = tt;
        }
    }
}

extern "C" void kernel_launch(void* const* d_in, const int* in_sizes, int n_in,
                              void* d_out, int out_size) {
    const int*   xcfg = nullptr;
    const float* T    = nullptr;
    for (int i = 0; i < n_in; ++i) {
        if (in_sizes[i] == 576) xcfg = (const int*)d_in[i];
        else                    T    = (const float*)d_in[i];
    }
    float* out = (float*)d_out;
    peps_quad2_kernel<<<32, NTH>>>(xcfg, T, out);
}

// round 12
// speedup vs baseline: 1.4060x; 1.4060x over previous
#include <cuda_runtime.h>
#include <cstdint>

// PEPS 6x6, D=3, B=16 — quadrant decomposition, cluster of 4 CTAs per config.
// rank 0=TL, 1=TR, 2=BL, 3=BR (bottom/right mirrored so all quadrants run
// identical code). Row 0 (sites 0-2) fused into a closed-form init; rows 1-2
// take 6 barrier-separated local steps (state = 243 float4 groups).
// Merge (R6-proven pull topology): rank0/rank2 pull peer S0 via DSMEM after a
// cluster barrier, compute M[v1,v2]; rank2 pushes M2 into rank0; rank0 dots.

#define NTH 256
#define ATF 108

__device__ __forceinline__ float dot3(float4 a, float4 b) {
    return a.x * b.x + a.y * b.y + a.z * b.z;
}

__device__ __forceinline__ uint32_t smem_u32(const void* p) {
    uint32_t a;
    asm("{ .reg .u64 t; cvta.to.shared.u64 t, %1; cvt.u32.u64 %0, t; }"
        : "=r"(a) : "l"(p));
    return a;
}

__device__ __forceinline__ float ld_cluster_f32(uint32_t laddr, uint32_t rank) {
    uint32_t r; float v;
    asm volatile("mapa.shared::cluster.u32 %0, %1, %2;" : "=r"(r) : "r"(laddr), "r"(rank));
    asm volatile("ld.shared::cluster.f32 %0, [%1];" : "=f"(v) : "r"(r) : "memory");
    return v;
}

__device__ __forceinline__ void st_cluster_f32(uint32_t laddr, uint32_t rank, float v) {
    uint32_t r;
    asm volatile("mapa.shared::cluster.u32 %0, %1, %2;" : "=r"(r) : "r"(laddr), "r"(rank));
    asm volatile("st.shared::cluster.f32 [%0], %1;" :: "r"(r), "f"(v) : "memory");
}

#define CLUSTER_BAR() do { \
    asm volatile("barrier.cluster.arrive.aligned;" ::: "memory"); \
    asm volatile("barrier.cluster.wait.aligned;"   ::: "memory"); \
} while (0)

__global__ __launch_bounds__(NTH, 1) __cluster_dims__(4, 1, 1)
void peps_quad_kernel(const int* __restrict__ xcfg,
                      const float* __restrict__ T,
                      float* __restrict__ out) {
    __shared__ float4 S0[243];
    __shared__ float4 S1[243];          // also peer-copy buffer in merge
    __shared__ float  At[9 * ATF];
    __shared__ float  M[729];           // my half's merged tensor (rank 0)
    __shared__ float  M2[729];          // bottom half's tensor (pushed by rank 2)
    __shared__ int    spins[36];
    __shared__ int    sOff[36];
    __shared__ float  red[8];

    const int t = threadIdx.x;
    const int b = blockIdx.x >> 2;
    uint32_t rank;
    asm("mov.u32 %0, %%cluster_ctarank;" : "=r"(rank));
    const int bottom = (int)(rank >> 1);
    const int right  = (int)(rank & 1);

    if (t < 36) spins[t] = xcfg[b * 36 + t];
    __syncthreads();
    if (t < 36) {
        int xx = t / 6, yy = t % 6;
        int p  = spins[t];
        int pu = (xx > 0) ? spins[t - 6] : 0;
        int pd = (xx < 5) ? spins[t + 6] : 0;
        int pl = (yy > 0) ? spins[t - 1] : 0;
        int pr = (yy < 5) ? spins[t + 1] : 0;
        sOff[t] = (((p * 2 + pu) * 2 + pd) * 2 + pl) * 2 + pr;
    }
    __syncthreads();

    // Gather my quadrant's 9 site tensors: At[s][o][hp][a][ln].
    for (int i = t; i < 9 * ATF; i += NTH) {
        int s = i / ATF, r = i - s * ATF;
        int o  = r / 36;  r -= o * 36;
        int hp = r / 12;  r -= hp * 12;
        int a  = r >> 2,  ln = r & 3;
        float v = 0.0f;
        if (ln < 3) {
            int x = bottom ? 5 - s / 3 : s / 3;
            int y = right  ? 5 - s % 3 : s % 3;
            int u  = bottom ? o : a;
            int d  = bottom ? a : o;
            int l  = right ? hp : ln;
            int rr = right ? ln : hp;
            int site = x * 6 + y;
            v = T[site * 2592 + (((u * 3 + d) * 3 + l) * 3 + rr) * 32 + sOff[site]];
        }
        At[i] = v;
    }
    __syncthreads();

    // Fused row 0 (sites 0,1,2): state(d0@81, d1@27, d2@9, r2@3) lanes=(v,0,0)
    //   v = sum_{h2} [ sum_{h1} A0[d0,h1] * A1[d1,h2,h1] ] * A2[d2,r2,h2]
    if (t < 243) {
        float v = 0.0f;
        if (t % 3 == 0) {
            int d0 = t / 81, d1 = (t / 27) % 3, d2 = (t / 9) % 3, r2 = (t / 3) % 3;
            const float* A0 = At + d0 * 36;                     // + h1*12
            const float* A1 = At + ATF + d1 * 36;               // + h2*12 + h1
            const float* A2 = At + 2 * ATF + d2 * 36 + r2 * 12; // + h2
            float w0 = A0[0] * A1[0]  + A0[12] * A1[1]  + A0[24] * A1[2];
            float w1 = A0[0] * A1[12] + A0[12] * A1[13] + A0[24] * A1[14];
            float w2 = A0[0] * A1[24] + A0[12] * A1[25] + A0[24] * A1[26];
            v = w0 * A2[0] + w1 * A2[1] + w2 * A2[2];
        }
        S0[t] = make_float4(v, 0.0f, 0.0f, 0.0f);
    }
    __syncthreads();

    // hoisted per-thread step indices
    const int d81 = t / 81,        b81 = t - d81 * 81;
    const int d27 = (t / 27) % 3,  b27 = t - d27 * 27;
    const int d9  = (t / 9) % 3,   b9  = t - d9 * 9;
    const int r3  = t % 3;
    const int bc4 = (t / 27) * 27 + ((t / 3) % 3) * 3;

    const float4* Atv = (const float4*)At;

#define STEPL(SITE, D_, BASE, S3, RD, WR) { \
    if (t < 243) { \
        float4 c0 = (RD)[BASE]; \
        float4 c1 = (RD)[BASE + (S3)]; \
        float4 c2 = (RD)[BASE + 2 * (S3)]; \
        const float4* Av = Atv + (SITE) * 27 + (D_) * 9; \
        float r0 = dot3(c0, Av[0]) + dot3(c1, Av[1]) + dot3(c2, Av[2]); \
        float r1 = dot3(c0, Av[3]) + dot3(c1, Av[4]) + dot3(c2, Av[5]); \
        float r2 = dot3(c0, Av[6]) + dot3(c1, Av[7]) + dot3(c2, Av[8]); \
        (WR)[t] = make_float4(r0, r1, r2, 0.0f); \
    } \
    __syncthreads(); \
}

#define STEPC4(SITE, RD, WR) { \
    if (t < 243) { \
        const float4* Av = Atv + (SITE) * 27 + d9 * 9 + r3 * 3; \
        float s_ = dot3((RD)[bc4], Av[0]) + dot3((RD)[bc4 + 9], Av[1]) \
                 + dot3((RD)[bc4 + 18], Av[2]); \
        (WR)[t] = make_float4(s_, 0.0f, 0.0f, 0.0f); \
    } \
    __syncthreads(); \
}

    // row 1
    STEPL (3, d81, b81, 81, S0, S1)
    STEPL (4, d27, b27, 27, S1, S0)
    STEPC4(5,               S0, S1)
    // row 2
    STEPL (6, d81, b81, 81, S1, S0)
    STEPL (7, d27, b27, 27, S0, S1)
    STEPL (8, d9,  b9,   9, S1, S0)   // final state in S0
#undef STEPL
#undef STEPC4

    CLUSTER_BAR();

    // Ranks 0 (top) and 2 (bottom): pull peer quadrant (rank+1) and merge.
    if (right == 0) {
        float* S1f = (float*)S1;
        uint32_t s0a = smem_u32(S0);
        for (int i = t; i < 972; i += NTH)
            S1f[i] = ld_cluster_f32(s0a + (uint32_t)i * 4u, rank + 1);
        __syncthreads();
        uint32_t m2a = smem_u32(M2);
        for (int v = t; v < 729; v += NTH) {
            int v1 = v / 27, v2 = v - 27 * (v / 27);
            const float4* L = S0 + v1 * 9;
            const float4* R = S1 + v2 * 9;
            float s = 0.0f;
            #pragma unroll
            for (int j = 0; j < 9; ++j) s += dot3(L[j], R[j]);
            if (bottom) st_cluster_f32(m2a + (uint32_t)v * 4u, 0, s);
            else        M[v] = s;
        }
    }
    CLUSTER_BAR();

    if (rank == 0) {
        float s = 0.0f;
        for (int v = t; v < 729; v += NTH) s += M[v] * M2[v];
        #pragma unroll
        for (int o = 16; o; o >>= 1) s += __shfl_xor_sync(0xFFFFFFFFu, s, o);
        if ((t & 31) == 0) red[t >> 5] = s;
        __syncthreads();
        if (t == 0) {
            float tt = 0.0f;
            #pragma unroll
            for (int w = 0; w < 8; ++w) tt += red[w];
            out[b] = tt;
        }
    }
}

extern "C" void kernel_launch(void* const* d_in, const int* in_sizes, int n_in,
                              void* d_out, int out_size) {
    const int*   xcfg = nullptr;
    const float* T    = nullptr;
    for (int i = 0; i < n_in; ++i) {
        if (in_sizes[i] == 576) xcfg = (const int*)d_in[i];
        else                    T    = (const float*)d_in[i];
    }
    float* out = (float*)d_out;
    peps_quad_kernel<<<64, NTH>>>(xcfg, T, out);
}